// round 13
// baseline (speedup 1.0000x reference)
#include <cuda_runtime.h>
#include <cuda_bf16.h>

// Problem constants (fixed by setup_inputs)
#define NN   8192      // nodes
#define INF  512       // in_features
#define HH   64        // hidden
#define DEG  32
#define EE   (NN * DEG)

#define NSCORE 128     // score blocks (indices 0..127 -> wave 1, no deadlock)
#define ROWS_PER_SCORE (NN / NSCORE)   // 64

// Scratch (__device__ globals; no allocation allowed)
__device__ float g_s1[NN];
__device__ float g_s2[NN];
__device__ int   g_count;      // reset by memset node before each replay

// ---------------------------------------------------------------------------
// Single fused kernel.
//  blocks 0..127   : score blocks. Compute v1=W@a[:H], v2=W@a[H:] in smem,
//                    then s1,s2 for 64 x-rows; fence; bump g_count.
//  blocks 128..8319: row blocks (row = blockIdx.x-128). Stream zero-fill of
//                    the 32KB row FIRST (no dependency), then warp 0 waits
//                    for g_count==NSCORE (long satisfied: score work ~5us,
//                    fill ~39us), loads scores via L2, writes the band.
// Low-index score blocks are scheduled in wave 1 alongside early row blocks,
// so the spin can always make progress. exp>0 => rowsum>0, no diag case.
// ---------------------------------------------------------------------------
__global__ void __launch_bounds__(256, 8)
k_fused(const float* __restrict__ x,
        const float* __restrict__ W,
        const float* __restrict__ a,
        const int*   __restrict__ ei,
        float* __restrict__ out)
{
    const int t = threadIdx.x;
    const int warp = t >> 5, lane = t & 31;

    if (blockIdx.x < NSCORE) {
        // ================= score block =================
        __shared__ float sa[2 * HH];
        __shared__ float sv1[INF];
        __shared__ float sv2[INF];

        if (t < 2 * HH) sa[t] = a[t];
        __syncthreads();

        // v1, v2: 8 warps x 64 W-rows, coalesced row loads + shuffle reduce
        for (int r = warp; r < INF; r += 8) {
            const float* wrow = W + (size_t)r * HH;
            float w0 = wrow[lane];
            float w1 = wrow[lane + 32];
            float acc1 = fmaf(w0, sa[lane],      w1 * sa[lane + 32]);
            float acc2 = fmaf(w0, sa[HH + lane], w1 * sa[HH + lane + 32]);
#pragma unroll
            for (int off = 16; off > 0; off >>= 1) {
                acc1 += __shfl_down_sync(0xffffffffu, acc1, off);
                acc2 += __shfl_down_sync(0xffffffffu, acc2, off);
            }
            if (lane == 0) { sv1[r] = acc1; sv2[r] = acc2; }
        }
        __syncthreads();

        // scores for 64 rows: warp handles 8 rows
        int row0 = blockIdx.x * ROWS_PER_SCORE + warp * 8;
        for (int j = 0; j < 8; ++j) {
            int row = row0 + j;
            const float4* xr = (const float4*)(x + (size_t)row * INF);
            float a1 = 0.f, a2 = 0.f;
#pragma unroll
            for (int i = 0; i < 4; ++i) {
                int idx = lane + 32 * i;
                float4 v = xr[idx];
                int b = idx * 4;
                a1 = fmaf(v.x, sv1[b + 0], a1);
                a1 = fmaf(v.y, sv1[b + 1], a1);
                a1 = fmaf(v.z, sv1[b + 2], a1);
                a1 = fmaf(v.w, sv1[b + 3], a1);
                a2 = fmaf(v.x, sv2[b + 0], a2);
                a2 = fmaf(v.y, sv2[b + 1], a2);
                a2 = fmaf(v.z, sv2[b + 2], a2);
                a2 = fmaf(v.w, sv2[b + 3], a2);
            }
#pragma unroll
            for (int off = 16; off > 0; off >>= 1) {
                a1 += __shfl_down_sync(0xffffffffu, a1, off);
                a2 += __shfl_down_sync(0xffffffffu, a2, off);
            }
            if (lane == 0) { g_s1[row] = a1; g_s2[row] = a2; }
        }

        // publish: make score writes visible, then bump the counter
        __syncthreads();
        __threadfence();
        if (t == 0) atomicAdd(&g_count, 1);
    } else {
        // ================= row block =================
        int s = blockIdx.x - NSCORE;
        float* row = out + (size_t)s * NN;

        // (1) streaming zero-fill first — no dependency on scores
        float4* r4 = (float4*)row;
        const float4 z = make_float4(0.f, 0.f, 0.f, 0.f);
#pragma unroll
        for (int i = 0; i < 8; ++i)
            __stcs(&r4[t + 256 * i], z);
        __syncthreads();

        // (2) warp 0: wait for scores (normally already done), write band
        if (warp == 0) {
            while (*((volatile int*)&g_count) < NSCORE) { }
            __threadfence();

            int e = s * DEG + lane;
            int d = __ldg(&ei[EE + e]);
            float v = __ldcg(&g_s1[s]) + __ldcg(&g_s2[d]);   // L2 loads
            v = (v >= 0.f) ? v : 0.1f * v;                   // leaky_relu 0.1
            float c = expf(v);
            float sum = c;
#pragma unroll
            for (int off = 16; off > 0; off >>= 1)
                sum += __shfl_xor_sync(0xffffffffu, sum, off);
            row[d] = c / sum;
        }
    }
}

extern "C" void kernel_launch(void* const* d_in, const int* in_sizes, int n_in,
                              void* d_out, int out_size)
{
    const float* x  = (const float*)d_in[0];   // [N, IN]
    const float* W  = (const float*)d_in[1];   // [IN, H]
    const float* a  = (const float*)d_in[2];   // [2H, 1]
    const int*   ei = (const int*)  d_in[3];   // [2, E]
    float* out = (float*)d_out;                // [N, N]

    // Reset the completion counter every replay (memset node in the graph).
    static void* cnt_addr = nullptr;
    if (!cnt_addr) cudaGetSymbolAddress(&cnt_addr, g_count);
    cudaMemsetAsync(cnt_addr, 0, sizeof(int));

    k_fused<<<NN + NSCORE, 256>>>(x, W, a, ei, out);
}

// round 14
// speedup vs baseline: 1.4219x; 1.4219x over previous
#include <cuda_runtime.h>
#include <cuda_bf16.h>

// Problem constants (fixed by setup_inputs)
#define NN   8192      // nodes
#define INF  512       // in_features
#define HH   64        // hidden
#define DEG  32
#define EE   (NN * DEG)

#define FRONT_BLOCKS 128
#define ROWS_PER_FB  (NN / FRONT_BLOCKS)   // 64

// Scratch (__device__ globals; no allocation allowed)
__device__ float g_s1[NN];
__device__ float g_s2[NN];

// ---------------------------------------------------------------------------
// K1 "front": projection + scores. 128 blocks x 512 threads.
// Every block fires the PDL trigger at entry so k_row launches immediately.
// Phase A: thread t computes v1[t] = W[t,:]@a[:H], v2[t] = W[t,:]@a[H:]
//          (16 float4 loads per thread -> MLP 16, latency-hidden; this fixes
//          R12's serialized warp-per-row version).
// Phase B: scores for 64 rows/block (4 rows per warp, float4 + shuffle).
// ---------------------------------------------------------------------------
__global__ void __launch_bounds__(512) k_front(const float* __restrict__ x,
                                               const float* __restrict__ W,
                                               const float* __restrict__ a)
{
    // Release the dependent fill kernel as early as possible.
    cudaTriggerProgrammaticLaunchCompletion();

    __shared__ float sa[2 * HH];
    __shared__ float sv1[INF];
    __shared__ float sv2[INF];

    const int t = threadIdx.x;
    const int warp = t >> 5, lane = t & 31;

    if (t < 2 * HH) sa[t] = a[t];
    __syncthreads();

    // ---- Phase A: v1, v2 — one W row per thread, 16 independent loads ---
    {
        const float4* wr = (const float4*)(W + (size_t)t * HH);
        float acc1 = 0.f, acc2 = 0.f;
#pragma unroll
        for (int i = 0; i < HH / 4; ++i) {
            float4 wv = wr[i];
            int b = 4 * i;
            acc1 = fmaf(wv.x, sa[b + 0], acc1);
            acc1 = fmaf(wv.y, sa[b + 1], acc1);
            acc1 = fmaf(wv.z, sa[b + 2], acc1);
            acc1 = fmaf(wv.w, sa[b + 3], acc1);
            acc2 = fmaf(wv.x, sa[HH + b + 0], acc2);
            acc2 = fmaf(wv.y, sa[HH + b + 1], acc2);
            acc2 = fmaf(wv.z, sa[HH + b + 2], acc2);
            acc2 = fmaf(wv.w, sa[HH + b + 3], acc2);
        }
        sv1[t] = acc1;
        sv2[t] = acc2;
    }
    __syncthreads();

    // ---- Phase B: scores for 64 rows (warp handles 4 consecutive rows) --
    int row0 = blockIdx.x * ROWS_PER_FB + warp * 4;
#pragma unroll
    for (int j = 0; j < 4; ++j) {
        int row = row0 + j;
        const float4* xr = (const float4*)(x + (size_t)row * INF);
        float a1 = 0.f, a2 = 0.f;
#pragma unroll
        for (int i = 0; i < 4; ++i) {
            int idx = lane + 32 * i;
            float4 v = xr[idx];
            int b = idx * 4;
            a1 = fmaf(v.x, sv1[b + 0], a1);
            a1 = fmaf(v.y, sv1[b + 1], a1);
            a1 = fmaf(v.z, sv1[b + 2], a1);
            a1 = fmaf(v.w, sv1[b + 3], a1);
            a2 = fmaf(v.x, sv2[b + 0], a2);
            a2 = fmaf(v.y, sv2[b + 1], a2);
            a2 = fmaf(v.z, sv2[b + 2], a2);
            a2 = fmaf(v.w, sv2[b + 3], a2);
        }
#pragma unroll
        for (int off = 16; off > 0; off >>= 1) {
            a1 += __shfl_down_sync(0xffffffffu, a1, off);
            a2 += __shfl_down_sync(0xffffffffu, a2, off);
        }
        if (lane == 0) { g_s1[row] = a1; g_s2[row] = a2; }
    }
}

// ---------------------------------------------------------------------------
// K2 "row": launched with programmatic stream serialization (PDL), so it
// starts while k_front is still running. One block per row s:
//   (1) stream unconditional float4 zeros over the 32KB row (no dependency),
//   (2) cudaGridDependencySynchronize() — HW wait for k_front completion
//       (satisfied long before the 39us fill ends),
//   (3) warp 0 computes the 32 normalized band coefficients and overwrites.
// exp > 0 => row sum > 0 always, so no zero-row diagonal case exists.
// ---------------------------------------------------------------------------
__global__ void __launch_bounds__(256) k_row(const int* __restrict__ ei,
                                             float* __restrict__ out)
{
    int s = blockIdx.x;
    int t = threadIdx.x;
    float* row = out + (size_t)s * NN;

    // (1) streaming zero-fill — the proven 39.4us / 6.8TB/s pattern
    float4* r4 = (float4*)row;
    const float4 z = make_float4(0.f, 0.f, 0.f, 0.f);
#pragma unroll
    for (int i = 0; i < 8; ++i)
        __stcs(&r4[t + 256 * i], z);

    // (2) wait for k_front (scores) — hardware dependency, no polling
    cudaGridDependencySynchronize();

    // (3) band write by warp 0
    if (t < DEG) {
        int e = s * DEG + t;
        int d = __ldg(&ei[EE + e]);
        float v = g_s1[s] + g_s2[d];
        v = (v >= 0.f) ? v : 0.1f * v;      // leaky_relu slope 0.1
        float c = expf(v);
        float sum = c;
#pragma unroll
        for (int off = 16; off > 0; off >>= 1)
            sum += __shfl_xor_sync(0xffffffffu, sum, off);
        row[d] = c / sum;
    }
}

extern "C" void kernel_launch(void* const* d_in, const int* in_sizes, int n_in,
                              void* d_out, int out_size)
{
    const float* x  = (const float*)d_in[0];   // [N, IN]
    const float* W  = (const float*)d_in[1];   // [IN, H]
    const float* a  = (const float*)d_in[2];   // [2H, 1]
    const int*   ei = (const int*)  d_in[3];   // [2, E]
    float* out = (float*)d_out;                // [N, N]

    // Front kernel: normal launch on the capture stream.
    k_front<<<FRONT_BLOCKS, 512>>>(x, W, a);

    // Fill kernel: PDL — launches as soon as k_front's blocks trigger.
    cudaLaunchConfig_t cfg = {};
    cfg.gridDim  = dim3(NN, 1, 1);
    cfg.blockDim = dim3(256, 1, 1);
    cfg.dynamicSmemBytes = 0;
    cfg.stream = 0;
    cudaLaunchAttribute attr[1];
    attr[0].id = cudaLaunchAttributeProgrammaticStreamSerialization;
    attr[0].val.programmaticStreamSerializationAllowed = 1;
    cfg.attrs = attr;
    cfg.numAttrs = 1;
    cudaLaunchKernelEx(&cfg, k_row, ei, out);
}